// round 14
// baseline (speedup 1.0000x reference)
#include <cuda_runtime.h>
#include <cstdint>

// Shapes (fixed by the problem)
#define Bq   256
#define Tq   512
#define Vq   100000
#define Eq   128
#define Hq   256
#define G3   768            // 3*H
#define XPW  1536           // 2 * 3H (forward | backward packed)
#define NTOK (Bq * Tq)      // 131072

// GRU partitioning: r rows per CTA, both directions
#define GRU_R    6
#define GRU_CPD  43                 // ceil(256/6) CTAs per direction
#define GRU_GRID (2 * GRU_CPD)      // 86
#define NCACHE   16                 // k-blocks of W_hh cached in smem (of 64)

// ---------------- scratch (static device globals; no runtime allocation) ---
__device__ float  g_xp[(size_t)NTOK * XPW];          // [T][B][1536]  (805 MB)
__device__ float4 g_wih4[(Eq / 4) * XPW];            // [32][1536] float4  (packed W_ih, k-blocked)
__device__ float4 g_whh4[2 * (Hq / 4) * G3];         // [2][64][768] float4 (packed W_hh, k-blocked)
__device__ float  g_hcat[Bq * 2 * Hq];               // [B][512] concat(hf, hb)

// ---------------- helpers --------------------------------------------------
__device__ __forceinline__ float sigmoid_f(float x) {
    return 1.0f / (1.0f + __expf(-x));
}
__device__ __forceinline__ float tanh_f(float x) {
    x = fminf(15.0f, fmaxf(-15.0f, x));
    float e = __expf(2.0f * x);
    return (e - 1.0f) / (e + 1.0f);
}
// packed fp32x2 FMA: d.lo += a.lo*b.lo; d.hi += a.hi*b.hi  (one issue slot, 2 MACs)
__device__ __forceinline__ void fma2(unsigned long long& d, unsigned long long a, unsigned long long b) {
    asm("fma.rn.f32x2 %0, %1, %2, %3;" : "=l"(d) : "l"(a), "l"(b), "l"(d));
}
__device__ __forceinline__ float f2sum(unsigned long long v) {
    return __uint_as_float((unsigned)v) + __uint_as_float((unsigned)(v >> 32));
}

// ---------------- K0: pack weights into k-blocked float4 layout ------------
__global__ void pack_kernel(const float* __restrict__ wih_f, const float* __restrict__ wih_b,
                            const float* __restrict__ whh_f, const float* __restrict__ whh_b) {
    int i = blockIdx.x * blockDim.x + threadIdx.x;
    const int n_ih = XPW * Eq;          // 196608
    const int n_hh = 2 * G3 * Hq;       // 393216
    if (i < n_ih) {
        int out = i / Eq, k = i % Eq;
        float v = (out < G3) ? wih_f[out * Eq + k] : wih_b[(out - G3) * Eq + k];
        ((float*)g_wih4)[((k >> 2) * XPW + out) * 4 + (k & 3)] = v;
    } else if (i < n_ih + n_hh) {
        int j = i - n_ih;
        int d = j / (G3 * Hq);
        int rem = j % (G3 * Hq);
        int out = rem / Hq, k = rem % Hq;
        const float* w = d ? whh_b : whh_f;
        ((float*)g_whh4)[((d * (Hq / 4) + (k >> 2)) * G3 + out) * 4 + (k & 3)] = w[out * Hq + k];
    }
}

// ---------------- K1: embedding gather + input projection (FFMA2) ----------
// Per CTA: 16 tokens x 1536 outputs, K=128. Two passes of 3 output-groups
// each (keeps f32x2 accumulators at 96 regs). k packed in pairs into f32x2.
__global__ void __launch_bounds__(256) proj_kernel(const int* __restrict__ x,
                                                   const float* __restrict__ emb,
                                                   const float* __restrict__ bih_f,
                                                   const float* __restrict__ bih_b) {
    __shared__ __align__(16) float s_emb[16][Eq];
    __shared__ int s_vid[16];
    const int tid = threadIdx.x;
    const int tok0 = blockIdx.x * 16;

    if (tid < 16) {
        int tok = tok0 + tid;
        int b = tok & (Bq - 1);
        int t = tok >> 8;
        s_vid[tid] = x[b * Tq + t];
    }
    __syncthreads();
#pragma unroll
    for (int i = 0; i < 8; ++i) {
        int idx = tid + i * 256;
        int m = idx >> 7, k = idx & 127;
        s_emb[m][k] = emb[(size_t)s_vid[m] * Eq + k];
    }
    __syncthreads();

    const int j = tid;
#pragma unroll 1
    for (int pass = 0; pass < 2; ++pass) {
        unsigned long long acc[3][16];
#pragma unroll
        for (int gg = 0; gg < 3; ++gg)
#pragma unroll
            for (int m = 0; m < 16; ++m) acc[gg][m] = 0ull;

#pragma unroll 2
        for (int kb = 0; kb < Eq / 4; ++kb) {
            ulonglong2 w[3];
#pragma unroll
            for (int gg = 0; gg < 3; ++gg)
                w[gg] = *(const ulonglong2*)&g_wih4[kb * XPW + (pass * 3 + gg) * 256 + j];
#pragma unroll
            for (int m = 0; m < 16; ++m) {
                ulonglong2 e = *(const ulonglong2*)&s_emb[m][kb * 4];
#pragma unroll
                for (int gg = 0; gg < 3; ++gg) {
                    fma2(acc[gg][m], w[gg].x, e.x);
                    fma2(acc[gg][m], w[gg].y, e.y);
                }
            }
        }

        float bv[3];
#pragma unroll
        for (int gg = 0; gg < 3; ++gg) {
            int out = (pass * 3 + gg) * 256 + j;
            bv[gg] = (out < G3) ? bih_f[out] : bih_b[out - G3];
        }
#pragma unroll
        for (int m = 0; m < 16; ++m) {
            float* dst = &g_xp[(size_t)(tok0 + m) * XPW];
#pragma unroll
            for (int gg = 0; gg < 3; ++gg)
                dst[(pass * 3 + gg) * 256 + j] = bv[gg] + f2sum(acc[gg][m]);
        }
    }
}

// ---------------- K2: GRU recurrence (persistent, batch-partitioned) -------
// Grid 86 = 2 dirs x 43 CTAs, 6 batch rows per CTA (last CTA/dir has 4).
// 256 threads; thread j owns hidden unit j. First NCACHE k-blocks of W_hh
// live in dynamic smem (192 KB); the rest stream from L2. FFMA2 throughout.
__global__ void __launch_bounds__(256) gru_kernel(const int* __restrict__ lengths,
                                                  const float* __restrict__ bhh_f,
                                                  const float* __restrict__ bhh_b) {
    extern __shared__ __align__(16) float4 s_w4[];       // [NCACHE][768] float4
    __shared__ __align__(16) float hs[GRU_R][Hq];
    const int tid = threadIdx.x;
    const int dir = blockIdx.x / GRU_CPD;
    const int c   = blockIdx.x % GRU_CPD;
    const int b0  = c * GRU_R;
    const int nr  = min(GRU_R, Bq - b0);

    const float4* __restrict__ Wg = g_whh4 + dir * ((Hq / 4) * G3);
    const float* __restrict__ bhh = dir ? bhh_b : bhh_f;

    // stage cached slice of W into smem
    for (int i = tid; i < NCACHE * G3; i += 256) s_w4[i] = Wg[i];

    int len[GRU_R], bb[GRU_R];
#pragma unroll
    for (int r = 0; r < GRU_R; ++r) {
        bb[r] = min(b0 + r, Bq - 1);
        len[r] = lengths[bb[r]];
    }
    for (int i = tid; i < GRU_R * Hq; i += 256) ((float*)hs)[i] = 0.0f;
    const float br = bhh[tid], bz = bhh[256 + tid], bn = bhh[512 + tid];
    __syncthreads();

    int t = dir ? (Tq - 1) : 0;
    const int stp = dir ? -1 : 1;

    for (int it = 0; it < Tq; ++it, t += stp) {
        // input projections for this step (issued early, consumed at the end)
        float xr[GRU_R], xz[GRU_R], xn[GRU_R];
#pragma unroll
        for (int r = 0; r < GRU_R; ++r) {
            const float* xq = &g_xp[(size_t)(t * Bq + bb[r]) * XPW + dir * G3];
            xr[r] = xq[tid];
            xz[r] = xq[256 + tid];
            xn[r] = xq[512 + tid];
        }

        unsigned long long ar[GRU_R], az[GRU_R], an[GRU_R];
#pragma unroll
        for (int r = 0; r < GRU_R; ++r) { ar[r] = 0ull; az[r] = 0ull; an[r] = 0ull; }

        // cached k-blocks (smem W)
#pragma unroll 2
        for (int kb = 0; kb < NCACHE; ++kb) {
            const ulonglong2 wr = *(const ulonglong2*)&s_w4[kb * G3 + tid];
            const ulonglong2 wz = *(const ulonglong2*)&s_w4[kb * G3 + 256 + tid];
            const ulonglong2 wn = *(const ulonglong2*)&s_w4[kb * G3 + 512 + tid];
#pragma unroll
            for (int r = 0; r < GRU_R; ++r) {
                const ulonglong2 h2 = *(const ulonglong2*)&hs[r][kb * 4];
                fma2(ar[r], wr.x, h2.x); fma2(ar[r], wr.y, h2.y);
                fma2(az[r], wz.x, h2.x); fma2(az[r], wz.y, h2.y);
                fma2(an[r], wn.x, h2.x); fma2(an[r], wn.y, h2.y);
            }
        }
        // streamed k-blocks (L2 W)
#pragma unroll 4
        for (int kb = NCACHE; kb < Hq / 4; ++kb) {
            const ulonglong2 wr = *(const ulonglong2*)&Wg[kb * G3 + tid];
            const ulonglong2 wz = *(const ulonglong2*)&Wg[kb * G3 + 256 + tid];
            const ulonglong2 wn = *(const ulonglong2*)&Wg[kb * G3 + 512 + tid];
#pragma unroll
            for (int r = 0; r < GRU_R; ++r) {
                const ulonglong2 h2 = *(const ulonglong2*)&hs[r][kb * 4];
                fma2(ar[r], wr.x, h2.x); fma2(ar[r], wr.y, h2.y);
                fma2(az[r], wz.x, h2.x); fma2(az[r], wz.y, h2.y);
                fma2(an[r], wn.x, h2.x); fma2(an[r], wn.y, h2.y);
            }
        }

        float hn_[GRU_R];
#pragma unroll
        for (int r = 0; r < GRU_R; ++r) {
            float rg = sigmoid_f(xr[r] + br + f2sum(ar[r]));
            float zg = sigmoid_f(xz[r] + bz + f2sum(az[r]));
            float ng = tanh_f(xn[r] + rg * (bn + f2sum(an[r])));   // b_hh_n inside r-gate
            float hold = hs[r][tid];
            float hnew = (1.0f - zg) * ng + zg * hold;
            hn_[r] = (t < len[r]) ? hnew : hold;
        }
        __syncthreads();   // all reads of hs for this step done
#pragma unroll
        for (int r = 0; r < GRU_R; ++r) hs[r][tid] = hn_[r];
        __syncthreads();   // hs updated before next step reads
    }

#pragma unroll
    for (int r = 0; r < GRU_R; ++r)
        if (r < nr) g_hcat[(b0 + r) * (2 * Hq) + dir * Hq + tid] = hs[r][tid];
}

// ---------------- K3: fc1 + relu + fc2 + L2 normalize ----------------------
__global__ void __launch_bounds__(256) head_kernel(const float* __restrict__ fc1_w,
                                                   const float* __restrict__ fc1_b,
                                                   const float* __restrict__ fc2_w,
                                                   const float* __restrict__ fc2_b,
                                                   float* __restrict__ out) {
    __shared__ float s_in[2 * Hq];
    __shared__ float s_hid[128];
    __shared__ float s_out[64];
    __shared__ float s_ss;
    const int b = blockIdx.x, tid = threadIdx.x;

    s_in[tid]       = g_hcat[b * 512 + tid];
    s_in[tid + 256] = g_hcat[b * 512 + 256 + tid];
    __syncthreads();

    const int w = tid >> 5, lane = tid & 31;
#pragma unroll
    for (int i = 0; i < 16; ++i) {
        int o = w * 16 + i;
        float p = 0.0f;
#pragma unroll
        for (int m = 0; m < 16; ++m) {
            int k = lane + m * 32;
            p += s_in[k] * fc1_w[o * 512 + k];
        }
#pragma unroll
        for (int s = 16; s > 0; s >>= 1) p += __shfl_xor_sync(0xffffffffu, p, s);
        if (lane == 0) s_hid[o] = fmaxf(p + fc1_b[o], 0.0f);
    }
    __syncthreads();

    if (w < 2) {
#pragma unroll
        for (int i = 0; i < 32; ++i) {
            int o = w * 32 + i;
            float p = 0.0f;
#pragma unroll
            for (int m = 0; m < 4; ++m) {
                int k = lane + m * 32;
                p += s_hid[k] * fc2_w[o * 128 + k];
            }
#pragma unroll
            for (int s = 16; s > 0; s >>= 1) p += __shfl_xor_sync(0xffffffffu, p, s);
            if (lane == 0) s_out[o] = p + fc2_b[o];
        }
    }
    __syncthreads();

    if (w == 0) {
        float v = s_out[lane] * s_out[lane] + s_out[lane + 32] * s_out[lane + 32];
#pragma unroll
        for (int s = 16; s > 0; s >>= 1) v += __shfl_xor_sync(0xffffffffu, v, s);
        if (lane == 0) s_ss = v;
    }
    __syncthreads();

    if (tid < 64) out[b * 64 + tid] = s_out[tid] / fmaxf(sqrtf(s_ss), 1e-12f);
}

// ---------------- launch ----------------------------------------------------
extern "C" void kernel_launch(void* const* d_in, const int* in_sizes, int n_in,
                              void* d_out, int out_size) {
    (void)in_sizes; (void)n_in; (void)out_size;
    const int*   x        = (const int*)d_in[0];
    const int*   lengths  = (const int*)d_in[1];
    const float* embedding= (const float*)d_in[2];
    const float* w_ih_f   = (const float*)d_in[3];
    const float* w_hh_f   = (const float*)d_in[4];
    const float* b_ih_f   = (const float*)d_in[5];
    const float* b_hh_f   = (const float*)d_in[6];
    const float* w_ih_b   = (const float*)d_in[7];
    const float* w_hh_b   = (const float*)d_in[8];
    const float* b_ih_b   = (const float*)d_in[9];
    const float* b_hh_b   = (const float*)d_in[10];
    const float* fc1_w    = (const float*)d_in[11];
    const float* fc1_b    = (const float*)d_in[12];
    const float* fc2_w    = (const float*)d_in[13];
    const float* fc2_b    = (const float*)d_in[14];
    float* out = (float*)d_out;

    // dynamic smem opt-in for the cached W slice (immediate API, not a stream op;
    // safe under graph capture, idempotent)
    static int smem_set = 0;
    if (!smem_set) {
        cudaFuncSetAttribute(gru_kernel, cudaFuncAttributeMaxDynamicSharedMemorySize,
                             NCACHE * G3 * (int)sizeof(float4));
        smem_set = 1;
    }

    pack_kernel<<<(XPW * Eq + 2 * G3 * Hq + 255) / 256, 256>>>(w_ih_f, w_ih_b, w_hh_f, w_hh_b);
    proj_kernel<<<NTOK / 16, 256>>>(x, embedding, b_ih_f, b_ih_b);
    gru_kernel<<<GRU_GRID, 256, NCACHE * G3 * sizeof(float4)>>>(lengths, b_hh_f, b_hh_b);
    head_kernel<<<Bq, 256>>>(fc1_w, fc1_b, fc2_w, fc2_b, out);
}

// round 15
// speedup vs baseline: 2.4535x; 2.4535x over previous
#include <cuda_runtime.h>
#include <cstdint>

// Shapes (fixed by the problem)
#define Bq   256
#define Tq   512
#define Vq   100000
#define Eq   128
#define Hq   256
#define G3   768            // 3*H
#define XPW  1536           // 2 * 3H (forward | backward packed)
#define NTOK (Bq * Tq)      // 131072

// GRU: clusters of 4 CTAs, 32 clusters (128 CTAs), 8 sorted rows per group,
// 32 groups per direction, pairing grp c (fwd) with 31-c (bwd) per cluster.
#define GCL      4
#define NGRP     32
#define ROWS_G   8
#define GRU_SMEM (64 * 192 * 16 + 2 * ROWS_G * Hq * 4)   // 196608 + 16384 = 212992

// ---------------- scratch (static device globals; no runtime allocation) ---
__device__ float  g_xp[(size_t)NTOK * XPW];          // [T][B][1536]  (805 MB)
__device__ float4 g_wih4[(Eq / 4) * XPW];            // [32][1536] float4 (packed W_ih)
__device__ float4 g_whh4[2 * (Hq / 4) * G3];         // [2][64][768] float4 (packed W_hh)
__device__ float  g_hcat[Bq * 2 * Hq];               // [B][512] concat(hf, hb)
__device__ int    g_perm[Bq];                        // batch rows sorted by length asc
__device__ int    g_slen[Bq];                        // sorted lengths

// ---------------- helpers --------------------------------------------------
__device__ __forceinline__ float sigmoid_f(float x) {
    return 1.0f / (1.0f + __expf(-x));
}
__device__ __forceinline__ float tanh_f(float x) {
    x = fminf(15.0f, fmaxf(-15.0f, x));
    float e = __expf(2.0f * x);
    return (e - 1.0f) / (e + 1.0f);
}
__device__ __forceinline__ unsigned cl_rank() {
    unsigned r; asm("mov.u32 %0, %%cluster_ctarank;" : "=r"(r)); return r;
}
__device__ __forceinline__ void cl_sync() {
    asm volatile("barrier.cluster.arrive.aligned;" ::: "memory");
    asm volatile("barrier.cluster.wait.aligned;"   ::: "memory");
}
__device__ __forceinline__ void dsmem_st_f32(unsigned laddr, unsigned rank, float v) {
    unsigned ra;
    asm volatile("mapa.shared::cluster.u32 %0, %1, %2;" : "=r"(ra) : "r"(laddr), "r"(rank));
    asm volatile("st.shared::cluster.f32 [%0], %1;" :: "r"(ra), "f"(v) : "memory");
}

// ---------------- K0: pack weights into k-blocked float4 layout ------------
__global__ void pack_kernel(const float* __restrict__ wih_f, const float* __restrict__ wih_b,
                            const float* __restrict__ whh_f, const float* __restrict__ whh_b) {
    int i = blockIdx.x * blockDim.x + threadIdx.x;
    const int n_ih = XPW * Eq;          // 196608
    const int n_hh = 2 * G3 * Hq;       // 393216
    if (i < n_ih) {
        int out = i / Eq, k = i % Eq;
        float v = (out < G3) ? wih_f[out * Eq + k] : wih_b[(out - G3) * Eq + k];
        ((float*)g_wih4)[((k >> 2) * XPW + out) * 4 + (k & 3)] = v;
    } else if (i < n_ih + n_hh) {
        int j = i - n_ih;
        int d = j / (G3 * Hq);
        int rem = j % (G3 * Hq);
        int out = rem / Hq, k = rem % Hq;
        const float* w = d ? whh_b : whh_f;
        ((float*)g_whh4)[((d * (Hq / 4) + (k >> 2)) * G3 + out) * 4 + (k & 3)] = w[out * Hq + k];
    }
}

// ---------------- K0b: sort batch rows by length (rank sort, 1 CTA) --------
__global__ void sort_kernel(const int* __restrict__ lengths) {
    __shared__ int sl[Bq];
    int b = threadIdx.x;
    sl[b] = lengths[b];
    __syncthreads();
    int len = sl[b], rank = 0;
#pragma unroll 8
    for (int j = 0; j < Bq; ++j) {
        int l2 = sl[j];
        rank += (l2 < len) || (l2 == len && j < b);
    }
    g_perm[rank] = b;
    g_slen[rank] = len;
}

// ---------------- K1: embedding gather + input projection ------------------
// Per CTA: one batch row b, 16 consecutive t's, 1536 outputs, K=128.
// Early-exit when t0 >= lengths[b] (GRU never reads masked-step xp values).
__global__ void __launch_bounds__(256) proj_kernel(const int* __restrict__ x,
                                                   const int* __restrict__ lengths,
                                                   const float* __restrict__ emb,
                                                   const float* __restrict__ bih_f,
                                                   const float* __restrict__ bih_b) {
    const int b  = blockIdx.x >> 5;
    const int t0 = (blockIdx.x & 31) << 4;
    if (t0 >= lengths[b]) return;            // whole tile masked downstream

    __shared__ __align__(16) float s_emb[16][Eq];
    __shared__ int s_vid[16];
    const int tid = threadIdx.x;

    if (tid < 16) s_vid[tid] = x[b * Tq + t0 + tid];
    __syncthreads();
#pragma unroll
    for (int i = 0; i < 8; ++i) {
        int idx = tid + i * 256;
        int m = idx >> 7, k = idx & 127;
        s_emb[m][k] = emb[(size_t)s_vid[m] * Eq + k];
    }
    __syncthreads();

    const int j = tid;
    float acc[6][16];
#pragma unroll
    for (int g = 0; g < 6; ++g) {
        int out = g * 256 + j;
        float bv = (out < G3) ? bih_f[out] : bih_b[out - G3];
#pragma unroll
        for (int m = 0; m < 16; ++m) acc[g][m] = bv;
    }

#pragma unroll 2
    for (int kb = 0; kb < Eq / 4; ++kb) {
        float4 w[6];
#pragma unroll
        for (int g = 0; g < 6; ++g) w[g] = g_wih4[kb * XPW + g * 256 + j];
#pragma unroll
        for (int m = 0; m < 16; ++m) {
            float4 e = *(const float4*)&s_emb[m][kb * 4];
#pragma unroll
            for (int g = 0; g < 6; ++g)
                acc[g][m] += w[g].x * e.x + w[g].y * e.y + w[g].z * e.z + w[g].w * e.w;
        }
    }

#pragma unroll
    for (int m = 0; m < 16; ++m) {
        float* dst = &g_xp[((size_t)(t0 + m) * Bq + b) * XPW];
#pragma unroll
        for (int g = 0; g < 6; ++g) dst[g * 256 + j] = acc[g][m];
    }
}

// ---------------- K2: GRU recurrence, cluster-resident W, sorted schedule --
// 128 CTAs = 32 clusters x 4. Each CTA holds a 192 KB W_hh slice in smem
// (its 64 hidden units x 3 gates, K=256), computes its h-slice for 8 rows,
// broadcasts it to peers via DSMEM, one cluster barrier per step.
// Jobs per cluster c: (fwd, group c) then (bwd, group 31-c); each job runs
// only to its group's max length (masked steps are exact no-ops).
__global__ void __launch_bounds__(256, 1) __cluster_dims__(GCL, 1, 1)
gru_kernel(const float* __restrict__ bhh_f, const float* __restrict__ bhh_b) {
    extern __shared__ __align__(16) unsigned char s_raw[];
    float4* s_w4 = (float4*)s_raw;                       // [64][192] float4
    float*  s_h  = (float*)(s_raw + 64 * 192 * 16);      // [2][8][256]
    __shared__ int s_row[ROWS_G], s_len[ROWS_G];

    const int tid  = threadIdx.x;
    const unsigned rank = cl_rank();
    const int cid  = blockIdx.x >> 2;                    // cluster id 0..31
    const int u    = tid & 63;
    const int rp   = tid >> 6;                           // 0..3
    const int rr0  = 2 * rp, rr1 = 2 * rp + 1;
    const int uglob = (int)rank * 64 + u;
    const unsigned hbase = (unsigned)__cvta_generic_to_shared(s_h);

    for (int job = 0; job < 2; ++job) {
        const int dir = job;
        const int grp = job ? (NGRP - 1 - cid) : cid;
        const float4* __restrict__ Wg = g_whh4 + dir * 64 * G3;
        const float* __restrict__ bhh = dir ? bhh_b : bhh_f;

        // stage this CTA's W slice: s_w4[k4*192 + gate*64 + uu]
        for (int i = tid; i < 64 * 192; i += 256) {
            int k4 = i / 192, jj = i % 192;
            int gate = jj >> 6, uu = jj & 63;
            s_w4[i] = Wg[k4 * G3 + gate * Hq + (int)rank * 64 + uu];
        }
        if (tid < ROWS_G) {
            s_row[tid] = g_perm[grp * ROWS_G + tid];
            s_len[tid] = g_slen[grp * ROWS_G + tid];
        }
        for (int i = tid; i < 2 * ROWS_G * Hq; i += 256) s_h[i] = 0.0f;
        __syncthreads();

        const int gmax = s_len[ROWS_G - 1];              // sorted asc -> max
        const float br = bhh[uglob], bz = bhh[Hq + uglob], bn = bhh[2 * Hq + uglob];
        const int b0r = s_row[rr0], b1r = s_row[rr1];
        const int l0  = s_len[rr0], l1  = s_len[rr1];
        cl_sync();                                       // W + h visible cluster-wide

        int p = 0;
        int t = dir ? (gmax - 1) : 0;
        const int stp = dir ? -1 : 1;

        for (int it = 0; it < gmax; ++it, t += stp) {
            // input projections (prefetched; consumed after the k-loop)
            const float* x0 = &g_xp[((size_t)t * Bq + b0r) * XPW + dir * G3 + uglob];
            const float* x1 = &g_xp[((size_t)t * Bq + b1r) * XPW + dir * G3 + uglob];
            float xr0 = x0[0], xz0 = x0[Hq], xn0 = x0[2 * Hq];
            float xr1 = x1[0], xz1 = x1[Hq], xn1 = x1[2 * Hq];

            float ar0 = 0.f, az0 = 0.f, an0 = 0.f;
            float ar1 = 0.f, az1 = 0.f, an1 = 0.f;
            const float* h0p = &s_h[(p * ROWS_G + rr0) * Hq];
            const float* h1p = &s_h[(p * ROWS_G + rr1) * Hq];

#pragma unroll 4
            for (int k4 = 0; k4 < 64; ++k4) {
                float4 wr = s_w4[k4 * 192 + u];
                float4 wz = s_w4[k4 * 192 + 64 + u];
                float4 wn = s_w4[k4 * 192 + 128 + u];
                float4 h0 = *(const float4*)&h0p[k4 * 4];   // broadcast within warp
                float4 h1 = *(const float4*)&h1p[k4 * 4];
                ar0 += wr.x * h0.x + wr.y * h0.y + wr.z * h0.z + wr.w * h0.w;
                az0 += wz.x * h0.x + wz.y * h0.y + wz.z * h0.z + wz.w * h0.w;
                an0 += wn.x * h0.x + wn.y * h0.y + wn.z * h0.z + wn.w * h0.w;
                ar1 += wr.x * h1.x + wr.y * h1.y + wr.z * h1.z + wr.w * h1.w;
                az1 += wz.x * h1.x + wz.y * h1.y + wz.z * h1.z + wz.w * h1.w;
                an1 += wn.x * h1.x + wn.y * h1.y + wn.z * h1.z + wn.w * h1.w;
            }

            float rg0 = sigmoid_f(xr0 + br + ar0);
            float zg0 = sigmoid_f(xz0 + bz + az0);
            float ng0 = tanh_f(xn0 + rg0 * (bn + an0));
            float ho0 = h0p[uglob];
            float hn0 = (t < l0) ? ((1.0f - zg0) * ng0 + zg0 * ho0) : ho0;

            float rg1 = sigmoid_f(xr1 + br + ar1);
            float zg1 = sigmoid_f(xz1 + bz + az1);
            float ng1 = tanh_f(xn1 + rg1 * (bn + an1));
            float ho1 = h1p[uglob];
            float hn1 = (t < l1) ? ((1.0f - zg1) * ng1 + zg1 * ho1) : ho1;

            // broadcast my (row, unit) results into every CTA's next-h buffer
            unsigned a0 = hbase + (((1 - p) * ROWS_G + rr0) * Hq + uglob) * 4u;
            unsigned a1 = hbase + (((1 - p) * ROWS_G + rr1) * Hq + uglob) * 4u;
#pragma unroll
            for (unsigned d = 0; d < GCL; ++d) {
                dsmem_st_f32(a0, d, hn0);
                dsmem_st_f32(a1, d, hn1);
            }
            cl_sync();                                   // writes visible; step done
            p ^= 1;
        }

        // final hidden state for this direction
        g_hcat[b0r * (2 * Hq) + dir * Hq + uglob] = s_h[(p * ROWS_G + rr0) * Hq + uglob];
        g_hcat[b1r * (2 * Hq) + dir * Hq + uglob] = s_h[(p * ROWS_G + rr1) * Hq + uglob];
        cl_sync();                                       // before smem reuse next job
    }
}

// ---------------- K3: fc1 + relu + fc2 + L2 normalize ----------------------
__global__ void __launch_bounds__(256) head_kernel(const float* __restrict__ fc1_w,
                                                   const float* __restrict__ fc1_b,
                                                   const float* __restrict__ fc2_w,
                                                   const float* __restrict__ fc2_b,
                                                   float* __restrict__ out) {
    __shared__ float s_in[2 * Hq];
    __shared__ float s_hid[128];
    __shared__ float s_out[64];
    __shared__ float s_ss;
    const int b = blockIdx.x, tid = threadIdx.x;

    s_in[tid]       = g_hcat[b * 512 + tid];
    s_in[tid + 256] = g_hcat[b * 512 + 256 + tid];
    __syncthreads();

    const int w = tid >> 5, lane = tid & 31;
#pragma unroll
    for (int i = 0; i < 16; ++i) {
        int o = w * 16 + i;
        float p = 0.0f;
#pragma unroll
        for (int m = 0; m < 16; ++m) {
            int k = lane + m * 32;
            p += s_in[k] * fc1_w[o * 512 + k];
        }
#pragma unroll
        for (int s = 16; s > 0; s >>= 1) p += __shfl_xor_sync(0xffffffffu, p, s);
        if (lane == 0) s_hid[o] = fmaxf(p + fc1_b[o], 0.0f);
    }
    __syncthreads();

    if (w < 2) {
#pragma unroll
        for (int i = 0; i < 32; ++i) {
            int o = w * 32 + i;
            float p = 0.0f;
#pragma unroll
            for (int m = 0; m < 4; ++m) {
                int k = lane + m * 32;
                p += s_hid[k] * fc2_w[o * 128 + k];
            }
#pragma unroll
            for (int s = 16; s > 0; s >>= 1) p += __shfl_xor_sync(0xffffffffu, p, s);
            if (lane == 0) s_out[o] = p + fc2_b[o];
        }
    }
    __syncthreads();

    if (w == 0) {
        float v = s_out[lane] * s_out[lane] + s_out[lane + 32] * s_out[lane + 32];
#pragma unroll
        for (int s = 16; s > 0; s >>= 1) v += __shfl_xor_sync(0xffffffffu, v, s);
        if (lane == 0) s_ss = v;
    }
    __syncthreads();

    if (tid < 64) out[b * 64 + tid] = s_out[tid] / fmaxf(sqrtf(s_ss), 1e-12f);
}

// ---------------- launch ----------------------------------------------------
extern "C" void kernel_launch(void* const* d_in, const int* in_sizes, int n_in,
                              void* d_out, int out_size) {
    (void)in_sizes; (void)n_in; (void)out_size;
    const int*   x        = (const int*)d_in[0];
    const int*   lengths  = (const int*)d_in[1];
    const float* embedding= (const float*)d_in[2];
    const float* w_ih_f   = (const float*)d_in[3];
    const float* w_hh_f   = (const float*)d_in[4];
    const float* b_ih_f   = (const float*)d_in[5];
    const float* b_hh_f   = (const float*)d_in[6];
    const float* w_ih_b   = (const float*)d_in[7];
    const float* w_hh_b   = (const float*)d_in[8];
    const float* b_ih_b   = (const float*)d_in[9];
    const float* b_hh_b   = (const float*)d_in[10];
    const float* fc1_w    = (const float*)d_in[11];
    const float* fc1_b    = (const float*)d_in[12];
    const float* fc2_w    = (const float*)d_in[13];
    const float* fc2_b    = (const float*)d_in[14];
    float* out = (float*)d_out;

    // opt-in to 208 KB dynamic smem for the GRU (idempotent, capture-safe)
    cudaFuncSetAttribute(gru_kernel, cudaFuncAttributeMaxDynamicSharedMemorySize, GRU_SMEM);

    pack_kernel<<<(XPW * Eq + 2 * G3 * Hq + 255) / 256, 256>>>(w_ih_f, w_ih_b, w_hh_f, w_hh_b);
    sort_kernel<<<1, Bq>>>(lengths);
    proj_kernel<<<Bq * 32, 256>>>(x, lengths, embedding, b_ih_f, b_ih_b);
    gru_kernel<<<NGRP * GCL, 256, GRU_SMEM>>>(b_hh_f, b_hh_b);
    head_kernel<<<Bq, 256>>>(fc1_w, fc1_b, fc2_w, fc2_b, out);
}

// round 16
// speedup vs baseline: 2.8536x; 1.1631x over previous
#include <cuda_runtime.h>
#include <cstdint>

// Shapes (fixed by the problem)
#define Bq   256
#define Tq   512
#define Vq   100000
#define Eq   128
#define Hq   256
#define G3   768            // 3*H
#define XPW  1536           // 2 * 3H (forward | backward packed)
#define NTOK (Bq * Tq)      // 131072

// GRU: clusters of 4 CTAs, 32 clusters (128 CTAs), 8 sorted rows per group,
// 32 groups per direction, pairing grp c (fwd) with 31-c (bwd) per cluster.
#define GCL      4
#define NGRP     32
#define ROWS_G   8
// dynamic smem: W 192K + h double-buffer 16K + partials 12K
#define SM_W     (64 * 192 * 16)                 // 196608
#define SM_H     (2 * ROWS_G * Hq * 4)           // 16384
#define SM_P     (ROWS_G * 3 * 2 * 64 * 4)       // 12288
#define GRU_SMEM (SM_W + SM_H + SM_P)            // 225280

// ---------------- scratch (static device globals; no runtime allocation) ---
__device__ float  g_xp[(size_t)NTOK * XPW];          // [T][B][1536]  (805 MB)
__device__ float4 g_wih4[(Eq / 4) * XPW];            // [32][1536] float4 (packed W_ih)
__device__ float4 g_whh4[2 * (Hq / 4) * G3];         // [2][64][768] float4 (packed W_hh)
__device__ float  g_hcat[Bq * 2 * Hq];               // [B][512] concat(hf, hb)
__device__ int    g_perm[Bq];                        // batch rows sorted by length asc
__device__ int    g_slen[Bq];                        // sorted lengths

// ---------------- helpers --------------------------------------------------
__device__ __forceinline__ float sigmoid_f(float x) {
    return 1.0f / (1.0f + __expf(-x));
}
__device__ __forceinline__ float tanh_f(float x) {
    x = fminf(15.0f, fmaxf(-15.0f, x));
    float e = __expf(2.0f * x);
    return (e - 1.0f) / (e + 1.0f);
}
__device__ __forceinline__ unsigned cl_rank() {
    unsigned r; asm("mov.u32 %0, %%cluster_ctarank;" : "=r"(r)); return r;
}
__device__ __forceinline__ void cl_sync() {
    asm volatile("barrier.cluster.arrive.aligned;" ::: "memory");
    asm volatile("barrier.cluster.wait.aligned;"   ::: "memory");
}
__device__ __forceinline__ void dsmem_st_f32(unsigned laddr, unsigned rank, float v) {
    unsigned ra;
    asm volatile("mapa.shared::cluster.u32 %0, %1, %2;" : "=r"(ra) : "r"(laddr), "r"(rank));
    asm volatile("st.shared::cluster.f32 [%0], %1;" :: "r"(ra), "f"(v) : "memory");
}

// ---------------- K0: pack weights into k-blocked float4 layout ------------
__global__ void pack_kernel(const float* __restrict__ wih_f, const float* __restrict__ wih_b,
                            const float* __restrict__ whh_f, const float* __restrict__ whh_b) {
    int i = blockIdx.x * blockDim.x + threadIdx.x;
    const int n_ih = XPW * Eq;          // 196608
    const int n_hh = 2 * G3 * Hq;       // 393216
    if (i < n_ih) {
        int out = i / Eq, k = i % Eq;
        float v = (out < G3) ? wih_f[out * Eq + k] : wih_b[(out - G3) * Eq + k];
        ((float*)g_wih4)[((k >> 2) * XPW + out) * 4 + (k & 3)] = v;
    } else if (i < n_ih + n_hh) {
        int j = i - n_ih;
        int d = j / (G3 * Hq);
        int rem = j % (G3 * Hq);
        int out = rem / Hq, k = rem % Hq;
        const float* w = d ? whh_b : whh_f;
        ((float*)g_whh4)[((d * (Hq / 4) + (k >> 2)) * G3 + out) * 4 + (k & 3)] = w[out * Hq + k];
    }
}

// ---------------- K0b: sort batch rows by length (rank sort, 1 CTA) --------
__global__ void sort_kernel(const int* __restrict__ lengths) {
    __shared__ int sl[Bq];
    int b = threadIdx.x;
    sl[b] = lengths[b];
    __syncthreads();
    int len = sl[b], rank = 0;
#pragma unroll 8
    for (int j = 0; j < Bq; ++j) {
        int l2 = sl[j];
        rank += (l2 < len) || (l2 == len && j < b);
    }
    g_perm[rank] = b;
    g_slen[rank] = len;
}

// ---------------- K1: embedding gather + input projection ------------------
// Per CTA: one batch row b, 16 consecutive t's, 1536 outputs, K=128.
// Early-exit when t0 >= lengths[b] (GRU never reads masked-step xp values).
__global__ void __launch_bounds__(256) proj_kernel(const int* __restrict__ x,
                                                   const int* __restrict__ lengths,
                                                   const float* __restrict__ emb,
                                                   const float* __restrict__ bih_f,
                                                   const float* __restrict__ bih_b) {
    const int b  = blockIdx.x >> 5;
    const int t0 = (blockIdx.x & 31) << 4;
    if (t0 >= lengths[b]) return;            // whole tile masked downstream

    __shared__ __align__(16) float s_emb[16][Eq];
    __shared__ int s_vid[16];
    const int tid = threadIdx.x;

    if (tid < 16) s_vid[tid] = x[b * Tq + t0 + tid];
    __syncthreads();
#pragma unroll
    for (int i = 0; i < 8; ++i) {
        int idx = tid + i * 256;
        int m = idx >> 7, k = idx & 127;
        s_emb[m][k] = emb[(size_t)s_vid[m] * Eq + k];
    }
    __syncthreads();

    const int j = tid;
    float acc[6][16];
#pragma unroll
    for (int g = 0; g < 6; ++g) {
        int out = g * 256 + j;
        float bv = (out < G3) ? bih_f[out] : bih_b[out - G3];
#pragma unroll
        for (int m = 0; m < 16; ++m) acc[g][m] = bv;
    }

#pragma unroll 2
    for (int kb = 0; kb < Eq / 4; ++kb) {
        float4 w[6];
#pragma unroll
        for (int g = 0; g < 6; ++g) w[g] = g_wih4[kb * XPW + g * 256 + j];
#pragma unroll
        for (int m = 0; m < 16; ++m) {
            float4 e = *(const float4*)&s_emb[m][kb * 4];
#pragma unroll
            for (int g = 0; g < 6; ++g)
                acc[g][m] += w[g].x * e.x + w[g].y * e.y + w[g].z * e.z + w[g].w * e.w;
        }
    }

#pragma unroll
    for (int m = 0; m < 16; ++m) {
        float* dst = &g_xp[((size_t)(t0 + m) * Bq + b) * XPW];
#pragma unroll
        for (int g = 0; g < 6; ++g) dst[g * 256 + j] = acc[g][m];
    }
}

// ---------------- K2: GRU recurrence, cluster-resident W, K-split ----------
// 128 CTAs = 32 clusters x 4. Each CTA holds a 192 KB W_hh slice in smem
// (its 64 hidden units x 3 gates, K=256). Threads = (u:64) x (rowhalf:2) x
// (Khalf:2): each computes partial dots for 4 rows over half of K (W smem
// traffic 2x resident instead of 4x). Partials reduced through a 12 KB smem
// buffer; 512 (row,u) pairs map 1:1 onto 2 reduction pairs per thread.
// h broadcast to cluster peers via DSMEM; one cluster barrier per step.
__global__ void __launch_bounds__(256, 1) __cluster_dims__(GCL, 1, 1)
gru_kernel(const float* __restrict__ bhh_f, const float* __restrict__ bhh_b) {
    extern __shared__ __align__(16) unsigned char s_raw[];
    float4* s_w4   = (float4*)s_raw;                     // [64 k4][gate*64+u]
    float*  s_h    = (float*)(s_raw + SM_W);             // [2][8][256]
    float*  s_part = (float*)(s_raw + SM_W + SM_H);      // [8 row][3 gate][2 kh][64 u]
    __shared__ int s_row[ROWS_G], s_len[ROWS_G];

    const int tid  = threadIdx.x;
    const unsigned rank = cl_rank();
    const int cid  = blockIdx.x >> 2;                    // cluster id 0..31
    const int u    = tid & 63;
    const int rh   = (tid >> 6) & 1;                     // row half (rows rh*4..+3)
    const int kh   = tid >> 7;                           // K half   (k4 in [kh*32, +32))
    const int uglob = (int)rank * 64 + u;
    const int prow0 = tid >> 6;                          // reduction pair rows
    const int prow1 = prow0 + 4;
    const unsigned hbase = (unsigned)__cvta_generic_to_shared(s_h);

    for (int job = 0; job < 2; ++job) {
        const int dir = job;
        const int grp = job ? (NGRP - 1 - cid) : cid;
        const float4* __restrict__ Wg = g_whh4 + dir * 64 * G3;
        const float* __restrict__ bhh = dir ? bhh_b : bhh_f;

        // stage this CTA's W slice: s_w4[k4*192 + gate*64 + uu]
        for (int i = tid; i < 64 * 192; i += 256) {
            int k4 = i / 192, jj = i % 192;
            int gate = jj >> 6, uu = jj & 63;
            s_w4[i] = Wg[k4 * G3 + gate * Hq + (int)rank * 64 + uu];
        }
        if (tid < ROWS_G) {
            s_row[tid] = g_perm[grp * ROWS_G + tid];
            s_len[tid] = g_slen[grp * ROWS_G + tid];
        }
        for (int i = tid; i < 2 * ROWS_G * Hq; i += 256) s_h[i] = 0.0f;
        __syncthreads();

        const int gmax = s_len[ROWS_G - 1];              // sorted asc -> group max
        const float br = bhh[uglob], bz = bhh[Hq + uglob], bn = bhh[2 * Hq + uglob];
        const int rb0 = s_row[prow0], rb1 = s_row[prow1];
        const int l0  = s_len[prow0], l1  = s_len[prow1];
        cl_sync();                                       // W + h visible cluster-wide

        int p = 0;
        int t = dir ? (gmax - 1) : 0;
        const int stp = dir ? -1 : 1;

        for (int it = 0; it < gmax; ++it, t += stp) {
            // prefetch x-projections for this thread's reduction pairs
            const float* x0 = &g_xp[((size_t)t * Bq + rb0) * XPW + dir * G3 + uglob];
            const float* x1 = &g_xp[((size_t)t * Bq + rb1) * XPW + dir * G3 + uglob];
            float xr0 = x0[0], xz0 = x0[Hq], xn0 = x0[2 * Hq];
            float xr1 = x1[0], xz1 = x1[Hq], xn1 = x1[2 * Hq];

            // partial dots: 4 rows (rh half) over K half (kh)
            float ar[4] = {0.f, 0.f, 0.f, 0.f};
            float az[4] = {0.f, 0.f, 0.f, 0.f};
            float an[4] = {0.f, 0.f, 0.f, 0.f};
            const float* hp = &s_h[(p * ROWS_G + rh * 4) * Hq];
            const int kb0 = kh * 32;

#pragma unroll 4
            for (int k4 = kb0; k4 < kb0 + 32; ++k4) {
                float4 wr = s_w4[k4 * 192 + u];
                float4 wz = s_w4[k4 * 192 + 64 + u];
                float4 wn = s_w4[k4 * 192 + 128 + u];
#pragma unroll
                for (int r = 0; r < 4; ++r) {
                    float4 h4 = *(const float4*)&hp[r * Hq + k4 * 4];  // broadcast
                    ar[r] += wr.x * h4.x + wr.y * h4.y + wr.z * h4.z + wr.w * h4.w;
                    az[r] += wz.x * h4.x + wz.y * h4.y + wz.z * h4.z + wz.w * h4.w;
                    an[r] += wn.x * h4.x + wn.y * h4.y + wn.z * h4.z + wn.w * h4.w;
                }
            }

#pragma unroll
            for (int r = 0; r < 4; ++r) {
                int row = rh * 4 + r;
                s_part[((row * 3 + 0) * 2 + kh) * 64 + u] = ar[r];
                s_part[((row * 3 + 1) * 2 + kh) * 64 + u] = az[r];
                s_part[((row * 3 + 2) * 2 + kh) * 64 + u] = an[r];
            }
            __syncthreads();                             // partials visible CTA-wide

            // reduce + gates for pair0 (prow0) and pair1 (prow1)
            float A0r = s_part[((prow0 * 3 + 0) * 2 + 0) * 64 + u] + s_part[((prow0 * 3 + 0) * 2 + 1) * 64 + u];
            float A0z = s_part[((prow0 * 3 + 1) * 2 + 0) * 64 + u] + s_part[((prow0 * 3 + 1) * 2 + 1) * 64 + u];
            float A0n = s_part[((prow0 * 3 + 2) * 2 + 0) * 64 + u] + s_part[((prow0 * 3 + 2) * 2 + 1) * 64 + u];
            float A1r = s_part[((prow1 * 3 + 0) * 2 + 0) * 64 + u] + s_part[((prow1 * 3 + 0) * 2 + 1) * 64 + u];
            float A1z = s_part[((prow1 * 3 + 1) * 2 + 0) * 64 + u] + s_part[((prow1 * 3 + 1) * 2 + 1) * 64 + u];
            float A1n = s_part[((prow1 * 3 + 2) * 2 + 0) * 64 + u] + s_part[((prow1 * 3 + 2) * 2 + 1) * 64 + u];

            float rg0 = sigmoid_f(xr0 + br + A0r);
            float zg0 = sigmoid_f(xz0 + bz + A0z);
            float ng0 = tanh_f(xn0 + rg0 * (bn + A0n));
            float ho0 = s_h[(p * ROWS_G + prow0) * Hq + uglob];
            float hn0 = (t < l0) ? ((1.0f - zg0) * ng0 + zg0 * ho0) : ho0;

            float rg1 = sigmoid_f(xr1 + br + A1r);
            float zg1 = sigmoid_f(xz1 + bz + A1z);
            float ng1 = tanh_f(xn1 + rg1 * (bn + A1n));
            float ho1 = s_h[(p * ROWS_G + prow1) * Hq + uglob];
            float hn1 = (t < l1) ? ((1.0f - zg1) * ng1 + zg1 * ho1) : ho1;

            // broadcast new h into every CTA's next-h buffer
            unsigned a0 = hbase + (((1 - p) * ROWS_G + prow0) * Hq + uglob) * 4u;
            unsigned a1 = hbase + (((1 - p) * ROWS_G + prow1) * Hq + uglob) * 4u;
#pragma unroll
            for (unsigned d = 0; d < GCL; ++d) {
                dsmem_st_f32(a0, d, hn0);
                dsmem_st_f32(a1, d, hn1);
            }
            cl_sync();                                   // writes visible; step done
            p ^= 1;
        }

        // final hidden state for this direction
        g_hcat[rb0 * (2 * Hq) + dir * Hq + uglob] = s_h[(p * ROWS_G + prow0) * Hq + uglob];
        g_hcat[rb1 * (2 * Hq) + dir * Hq + uglob] = s_h[(p * ROWS_G + prow1) * Hq + uglob];
        cl_sync();                                       // before smem reuse next job
    }
}

// ---------------- K3: fc1 + relu + fc2 + L2 normalize ----------------------
__global__ void __launch_bounds__(256) head_kernel(const float* __restrict__ fc1_w,
                                                   const float* __restrict__ fc1_b,
                                                   const float* __restrict__ fc2_w,
                                                   const float* __restrict__ fc2_b,
                                                   float* __restrict__ out) {
    __shared__ float s_in[2 * Hq];
    __shared__ float s_hid[128];
    __shared__ float s_out[64];
    __shared__ float s_ss;
    const int b = blockIdx.x, tid = threadIdx.x;

    s_in[tid]       = g_hcat[b * 512 + tid];
    s_in[tid + 256] = g_hcat[b * 512 + 256 + tid];
    __syncthreads();

    const int w = tid >> 5, lane = tid & 31;
#pragma unroll
    for (int i = 0; i < 16; ++i) {
        int o = w * 16 + i;
        float p = 0.0f;
#pragma unroll
        for (int m = 0; m < 16; ++m) {
            int k = lane + m * 32;
            p += s_in[k] * fc1_w[o * 512 + k];
        }
#pragma unroll
        for (int s = 16; s > 0; s >>= 1) p += __shfl_xor_sync(0xffffffffu, p, s);
        if (lane == 0) s_hid[o] = fmaxf(p + fc1_b[o], 0.0f);
    }
    __syncthreads();

    if (w < 2) {
#pragma unroll
        for (int i = 0; i < 32; ++i) {
            int o = w * 32 + i;
            float p = 0.0f;
#pragma unroll
            for (int m = 0; m < 4; ++m) {
                int k = lane + m * 32;
                p += s_hid[k] * fc2_w[o * 128 + k];
            }
#pragma unroll
            for (int s = 16; s > 0; s >>= 1) p += __shfl_xor_sync(0xffffffffu, p, s);
            if (lane == 0) s_out[o] = p + fc2_b[o];
        }
    }
    __syncthreads();

    if (w == 0) {
        float v = s_out[lane] * s_out[lane] + s_out[lane + 32] * s_out[lane + 32];
#pragma unroll
        for (int s = 16; s > 0; s >>= 1) v += __shfl_xor_sync(0xffffffffu, v, s);
        if (lane == 0) s_ss = v;
    }
    __syncthreads();

    if (tid < 64) out[b * 64 + tid] = s_out[tid] / fmaxf(sqrtf(s_ss), 1e-12f);
}

// ---------------- launch ----------------------------------------------------
extern "C" void kernel_launch(void* const* d_in, const int* in_sizes, int n_in,
                              void* d_out, int out_size) {
    (void)in_sizes; (void)n_in; (void)out_size;
    const int*   x        = (const int*)d_in[0];
    const int*   lengths  = (const int*)d_in[1];
    const float* embedding= (const float*)d_in[2];
    const float* w_ih_f   = (const float*)d_in[3];
    const float* w_hh_f   = (const float*)d_in[4];
    const float* b_ih_f   = (const float*)d_in[5];
    const float* b_hh_f   = (const float*)d_in[6];
    const float* w_ih_b   = (const float*)d_in[7];
    const float* w_hh_b   = (const float*)d_in[8];
    const float* b_ih_b   = (const float*)d_in[9];
    const float* b_hh_b   = (const float*)d_in[10];
    const float* fc1_w    = (const float*)d_in[11];
    const float* fc1_b    = (const float*)d_in[12];
    const float* fc2_w    = (const float*)d_in[13];
    const float* fc2_b    = (const float*)d_in[14];
    float* out = (float*)d_out;

    // opt-in to 220 KB dynamic smem for the GRU (idempotent, capture-safe)
    cudaFuncSetAttribute(gru_kernel, cudaFuncAttributeMaxDynamicSharedMemorySize, GRU_SMEM);

    pack_kernel<<<(XPW * Eq + 2 * G3 * Hq + 255) / 256, 256>>>(w_ih_f, w_ih_b, w_hh_f, w_hh_b);
    sort_kernel<<<1, Bq>>>(lengths);
    proj_kernel<<<Bq * 32, 256>>>(x, lengths, embedding, b_ih_f, b_ih_b);
    gru_kernel<<<NGRP * GCL, 256, GRU_SMEM>>>(b_hh_f, b_hh_b);
    head_kernel<<<Bq, 256>>>(fc1_w, fc1_b, fc2_w, fc2_b, out);
}